// round 11
// baseline (speedup 1.0000x reference)
#include <cuda_runtime.h>
#include <cuda_fp16.h>

// GravityDecoder, two-phase with PDL (R9 byte layout, higher-MLP K2):
//   K1: zh = fp16(z) + m[n] = dot(z[n],W)+b (fp32).
//   K2: 2 lanes/edge x 16 edges/warp -> 16 LDG.128 in flight per thread,
//       384 outstanding gathers/SM at 3 blocks/SM. m_j gathered (fp32).

#define MAX_N 100000
__device__ static uint4 g_zh[MAX_N * 16];   // fp16 z rows: 256 B/row
__device__ static float g_m[MAX_N];         // m = z@W + b

#define WARPS_PER_BLOCK 8
#define THREADS (WARPS_PER_BLOCK * 32)

// ---------------- Kernel 1: convert z to fp16 + precompute m ----------------
__global__ __launch_bounds__(THREADS) void precompute_kernel(
    const float* __restrict__ z,
    const float* __restrict__ W,
    const float* __restrict__ b_ptr,
    int N)
{
    const int lane   = threadIdx.x & 31;
    const int warp   = (int)((blockIdx.x * (unsigned)blockDim.x + threadIdx.x) >> 5);
    const int nwarps = (int)((gridDim.x * (unsigned)blockDim.x) >> 5);

    const float b = *b_ptr;
    const float4 w4 = reinterpret_cast<const float4*>(W)[lane];

    int row = warp;
    if (row < N) {
        float4 v = reinterpret_cast<const float4*>(z + (size_t)row * 128)[lane];
        for (; row < N; ) {
            const int next = row + nwarps;
            float4 vn;
            if (next < N)
                vn = reinterpret_cast<const float4*>(z + (size_t)next * 128)[lane];

            float mj = v.x * w4.x + v.y * w4.y + v.z * w4.z + v.w * w4.w;
            #pragma unroll
            for (int off = 16; off > 0; off >>= 1)
                mj += __shfl_xor_sync(0xffffffffu, mj, off);
            if (lane == 0) g_m[row] = mj + b;

            const __half2 lo = __floats2half2_rn(v.x, v.y);
            const __half2 hi = __floats2half2_rn(v.z, v.w);
            uint2 packed;
            packed.x = *reinterpret_cast<const unsigned*>(&lo);
            packed.y = *reinterpret_cast<const unsigned*>(&hi);
            reinterpret_cast<uint2*>(g_zh)[(size_t)row * 32 + lane] = packed;

            row = next;
            v   = vn;
        }
    }
    cudaTriggerProgrammaticLaunchCompletion();
}

// ---------------- Kernel 2: per-edge distance + outputs ----------------
__device__ __forceinline__ float d2_accum(uint4 A, uint4 C, float acc)
{
    const unsigned* pa = &A.x;
    const unsigned* pc = &C.x;
    #pragma unroll
    for (int k = 0; k < 4; k++) {
        const __half2 ha = *reinterpret_cast<const __half2*>(&pa[k]);
        const __half2 hc = *reinterpret_cast<const __half2*>(&pc[k]);
        const __half2 d  = __hsub2(ha, hc);
        const float2  df = __half22float2(d);
        acc += df.x * df.x + df.y * df.y;
    }
    return acc;
}

__global__ __launch_bounds__(THREADS, 3) void gravity_decoder_kernel(
    const int* __restrict__ edge_index,
    float* __restrict__ out,
    int E)
{
    const int lane   = threadIdx.x & 31;
    const int sub    = lane & 1;        // 2 lanes per edge
    const int group  = lane >> 1;       // 0..15 : which edge of the 16
    const int warp   = (int)((blockIdx.x * (unsigned)blockDim.x + threadIdx.x) >> 5);
    const int nwarps = (int)((gridDim.x * (unsigned)blockDim.x) >> 5);
    const int stride = nwarps * 16;

    float* __restrict__ out_logits = out;
    float* __restrict__ out_prob   = out + (size_t)E;
    float* __restrict__ out_mj     = out + 2 * (size_t)E;
    float* __restrict__ out_d2     = out + 3 * (size_t)E;

    int e16 = warp * 16;
    if (e16 >= E) {
        cudaGridDependencySynchronize();
        return;
    }

    // Prologue index loads (independent of K1) before the dependency sync.
    int e  = e16 + group;
    int es = (e < E) ? e : (E - 1);
    int src = __ldcs(edge_index + es);
    int dst = __ldcs(edge_index + es + (size_t)E);

    cudaGridDependencySynchronize();   // g_zh / g_m valid after this

    for (; e16 < E; e16 += stride) {
        const int  ecur  = e16 + group;
        const bool alive = (ecur < E);

        const uint4* __restrict__ zi = g_zh + (size_t)src * 16;
        const uint4* __restrict__ zj = g_zh + (size_t)dst * 16;

        // 16 LDG.128 in flight per thread: 2 lanes x 8 uint4 cover a 256B row
        uint4 A[8], C[8];
        #pragma unroll
        for (int k = 0; k < 8; k++) A[k] = zi[sub + 2 * k];
        #pragma unroll
        for (int k = 0; k < 8; k++) C[k] = zj[sub + 2 * k];

        // m_j: same address for both lanes -> broadcast
        const float mj = __ldg(g_m + dst);

        // Prefetch next iteration's indices while gathers are in flight
        const int e16n = e16 + stride;
        if (e16n < E) {
            const int en  = e16n + group;
            const int esn = (en < E) ? en : (E - 1);
            src = __ldcs(edge_index + esn);
            dst = __ldcs(edge_index + esn + (size_t)E);
        }

        float d2 = 0.0f;
        #pragma unroll
        for (int k = 0; k < 8; k++) d2 = d2_accum(A[k], C[k], d2);

        // 1-step reduce across the 2 lanes
        d2 += __shfl_xor_sync(0xffffffffu, d2, 1);

        d2 += 1e-7f;
        const float logit = mj - __logf(d2);

        if (alive) {
            if (sub == 0) {
                __stcs(out_logits + ecur, logit);
                __stcs(out_mj + ecur, mj);
            } else {
                __stcs(out_prob + ecur, __fdividef(1.0f, 1.0f + __expf(-logit)));
                __stcs(out_d2 + ecur, d2);
            }
        }
    }
}

extern "C" void kernel_launch(void* const* d_in, const int* in_sizes, int n_in,
                              void* d_out, int out_size)
{
    const float* z   = (const float*)d_in[0];
    const int*   ei  = (const int*)d_in[1];
    const float* W   = (const float*)d_in[2];
    const float* b   = (const float*)d_in[3];
    float*       out = (float*)d_out;

    const int N = in_sizes[0] / 128;
    const int E = in_sizes[1] / 2;

    // K1: persistent grid-stride
    int blocks1 = (N + WARPS_PER_BLOCK - 1) / WARPS_PER_BLOCK;
    if (blocks1 > 1480) blocks1 = 1480;
    precompute_kernel<<<blocks1, THREADS>>>(z, W, b, N);

    // K2: 16 edges per warp, PDL overlap with K1 tail
    int blocks2 = (E + WARPS_PER_BLOCK * 16 - 1) / (WARPS_PER_BLOCK * 16);

    cudaLaunchConfig_t cfg = {};
    cfg.gridDim  = dim3((unsigned)blocks2, 1, 1);
    cfg.blockDim = dim3(THREADS, 1, 1);
    cfg.dynamicSmemBytes = 0;
    cfg.stream = 0;
    cudaLaunchAttribute attrs[1];
    attrs[0].id = cudaLaunchAttributeProgrammaticStreamSerialization;
    attrs[0].val.programmaticStreamSerializationAllowed = 1;
    cfg.attrs = attrs;
    cfg.numAttrs = 1;
    cudaLaunchKernelEx(&cfg, gravity_decoder_kernel, ei, out, E);
}

// round 12
// speedup vs baseline: 1.2950x; 1.2950x over previous
#include <cuda_runtime.h>
#include <cuda_fp16.h>

// GravityDecoder, two-phase with PDL:
//   K1: zh = fp16(z) + m[n] = dot(z[n],W)+b (fp32).
//   K2: 8 lanes/edge (full-128B-line coalescing, 4 L1 wavefronts/edge),
//       2 edges batched per thread -> 8 LDG.128 in flight, 5 blocks/SM.

#define MAX_N 100000
__device__ static uint4 g_zh[MAX_N * 16];   // fp16 z rows: 256 B/row
__device__ static float g_m[MAX_N];         // m = z@W + b

#define WARPS_PER_BLOCK 8
#define THREADS (WARPS_PER_BLOCK * 32)

// ---------------- Kernel 1: convert z to fp16 + precompute m ----------------
__global__ __launch_bounds__(THREADS) void precompute_kernel(
    const float* __restrict__ z,
    const float* __restrict__ W,
    const float* __restrict__ b_ptr,
    int N)
{
    const int lane   = threadIdx.x & 31;
    const int warp   = (int)((blockIdx.x * (unsigned)blockDim.x + threadIdx.x) >> 5);
    const int nwarps = (int)((gridDim.x * (unsigned)blockDim.x) >> 5);

    const float b = *b_ptr;
    const float4 w4 = reinterpret_cast<const float4*>(W)[lane];

    int row = warp;
    if (row < N) {
        float4 v = reinterpret_cast<const float4*>(z + (size_t)row * 128)[lane];
        for (; row < N; ) {
            const int next = row + nwarps;
            float4 vn;
            if (next < N)
                vn = reinterpret_cast<const float4*>(z + (size_t)next * 128)[lane];

            float mj = v.x * w4.x + v.y * w4.y + v.z * w4.z + v.w * w4.w;
            #pragma unroll
            for (int off = 16; off > 0; off >>= 1)
                mj += __shfl_xor_sync(0xffffffffu, mj, off);
            if (lane == 0) g_m[row] = mj + b;

            const __half2 lo = __floats2half2_rn(v.x, v.y);
            const __half2 hi = __floats2half2_rn(v.z, v.w);
            uint2 packed;
            packed.x = *reinterpret_cast<const unsigned*>(&lo);
            packed.y = *reinterpret_cast<const unsigned*>(&hi);
            reinterpret_cast<uint2*>(g_zh)[(size_t)row * 32 + lane] = packed;

            row = next;
            v   = vn;
        }
    }
    cudaTriggerProgrammaticLaunchCompletion();
}

// ---------------- Kernel 2: per-edge distance + outputs ----------------
__device__ __forceinline__ float d2_accum(uint4 A, uint4 C, float acc)
{
    const unsigned* pa = &A.x;
    const unsigned* pc = &C.x;
    #pragma unroll
    for (int k = 0; k < 4; k++) {
        const __half2 ha = *reinterpret_cast<const __half2*>(&pa[k]);
        const __half2 hc = *reinterpret_cast<const __half2*>(&pc[k]);
        const __half2 d  = __hsub2(ha, hc);
        const float2  df = __half22float2(d);
        acc += df.x * df.x + df.y * df.y;
    }
    return acc;
}

__global__ __launch_bounds__(THREADS, 5) void gravity_decoder_kernel(
    const int* __restrict__ edge_index,
    float* __restrict__ out,
    int E)
{
    const int lane   = threadIdx.x & 31;
    const int sub    = lane & 7;        // sublane within 8-lane group
    const int group  = lane >> 3;       // 0..3
    const int warp   = (int)((blockIdx.x * (unsigned)blockDim.x + threadIdx.x) >> 5);
    const int nwarps = (int)((gridDim.x * (unsigned)blockDim.x) >> 5);
    const int stride = nwarps * 8;      // 8 edges per warp per iteration

    float* __restrict__ out_logits = out;
    float* __restrict__ out_prob   = out + (size_t)E;
    float* __restrict__ out_mj     = out + 2 * (size_t)E;
    float* __restrict__ out_d2     = out + 3 * (size_t)E;

    int e8 = warp * 8;
    if (e8 >= E) {
        cudaGridDependencySynchronize();
        return;
    }

    // Prologue: indices for edges (e8+group) and (e8+group+4) — independent
    // of K1, issued before the dependency sync.
    int ea  = e8 + group;
    int eb  = e8 + group + 4;
    int esa = (ea < E) ? ea : (E - 1);
    int esb = (eb < E) ? eb : (E - 1);
    int src0 = __ldcs(edge_index + esa);
    int dst0 = __ldcs(edge_index + esa + (size_t)E);
    int src1 = __ldcs(edge_index + esb);
    int dst1 = __ldcs(edge_index + esb + (size_t)E);

    cudaGridDependencySynchronize();   // g_zh / g_m valid after this

    for (; e8 < E; e8 += stride) {
        const int  e0     = e8 + group;
        const int  e1     = e8 + group + 4;
        const bool alive0 = (e0 < E);
        const bool alive1 = (e1 < E);

        const uint4* __restrict__ zi0 = g_zh + (size_t)src0 * 16;
        const uint4* __restrict__ zj0 = g_zh + (size_t)dst0 * 16;
        const uint4* __restrict__ zi1 = g_zh + (size_t)src1 * 16;
        const uint4* __restrict__ zj1 = g_zh + (size_t)dst1 * 16;

        // 8 LDG.128 in flight; each warp instruction covers 4 full 128B lines
        const uint4 A00 = zi0[sub];
        const uint4 A01 = zi0[sub + 8];
        const uint4 C00 = zj0[sub];
        const uint4 C01 = zj0[sub + 8];
        const uint4 A10 = zi1[sub];
        const uint4 A11 = zi1[sub + 8];
        const uint4 C10 = zj1[sub];
        const uint4 C11 = zj1[sub + 8];

        const float mj0 = __ldg(g_m + dst0);
        const float mj1 = __ldg(g_m + dst1);

        // Prefetch next iteration's indices while gathers are in flight
        const int e8n = e8 + stride;
        if (e8n < E) {
            const int ena  = e8n + group;
            const int enb  = e8n + group + 4;
            const int esna = (ena < E) ? ena : (E - 1);
            const int esnb = (enb < E) ? enb : (E - 1);
            src0 = __ldcs(edge_index + esna);
            dst0 = __ldcs(edge_index + esna + (size_t)E);
            src1 = __ldcs(edge_index + esnb);
            dst1 = __ldcs(edge_index + esnb + (size_t)E);
        }

        float d20 = 0.0f, d21 = 0.0f;
        d20 = d2_accum(A00, C00, d20);
        d20 = d2_accum(A01, C01, d20);
        d21 = d2_accum(A10, C10, d21);
        d21 = d2_accum(A11, C11, d21);

        // 3-step butterfly within each 8-lane group, both edges interleaved
        #pragma unroll
        for (int off = 4; off > 0; off >>= 1) {
            d20 += __shfl_xor_sync(0xffffffffu, d20, off);
            d21 += __shfl_xor_sync(0xffffffffu, d21, off);
        }

        d20 += 1e-7f;
        d21 += 1e-7f;
        const float logit0 = mj0 - __logf(d20);
        const float logit1 = mj1 - __logf(d21);

        // 8 sublanes handle the 8 scalar stores (4 per edge)
        if (sub < 4) {
            if (alive0) {
                if (sub == 0)      __stcs(out_logits + e0, logit0);
                else if (sub == 1) __stcs(out_prob + e0, __fdividef(1.0f, 1.0f + __expf(-logit0)));
                else if (sub == 2) __stcs(out_mj + e0, mj0);
                else               __stcs(out_d2 + e0, d20);
            }
        } else {
            if (alive1) {
                if (sub == 4)      __stcs(out_logits + e1, logit1);
                else if (sub == 5) __stcs(out_prob + e1, __fdividef(1.0f, 1.0f + __expf(-logit1)));
                else if (sub == 6) __stcs(out_mj + e1, mj1);
                else               __stcs(out_d2 + e1, d21);
            }
        }
    }
}

extern "C" void kernel_launch(void* const* d_in, const int* in_sizes, int n_in,
                              void* d_out, int out_size)
{
    const float* z   = (const float*)d_in[0];
    const int*   ei  = (const int*)d_in[1];
    const float* W   = (const float*)d_in[2];
    const float* b   = (const float*)d_in[3];
    float*       out = (float*)d_out;

    const int N = in_sizes[0] / 128;
    const int E = in_sizes[1] / 2;

    // K1: persistent grid-stride
    int blocks1 = (N + WARPS_PER_BLOCK - 1) / WARPS_PER_BLOCK;
    if (blocks1 > 1480) blocks1 = 1480;
    precompute_kernel<<<blocks1, THREADS>>>(z, W, b, N);

    // K2: 8 edges per warp per iteration, PDL overlap with K1 tail
    int blocks2 = (E + WARPS_PER_BLOCK * 8 - 1) / (WARPS_PER_BLOCK * 8);
    if (blocks2 > 4736) blocks2 = 4736;

    cudaLaunchConfig_t cfg = {};
    cfg.gridDim  = dim3((unsigned)blocks2, 1, 1);
    cfg.blockDim = dim3(THREADS, 1, 1);
    cfg.dynamicSmemBytes = 0;
    cfg.stream = 0;
    cudaLaunchAttribute attrs[1];
    attrs[0].id = cudaLaunchAttributeProgrammaticStreamSerialization;
    attrs[0].val.programmaticStreamSerializationAllowed = 1;
    cfg.attrs = attrs;
    cfg.numAttrs = 1;
    cudaLaunchKernelEx(&cfg, gravity_decoder_kernel, ei, out, E);
}

// round 13
// speedup vs baseline: 1.3757x; 1.0623x over previous
#include <cuda_runtime.h>
#include <cuda_fp16.h>

// GravityDecoder, two-phase with PDL:
//   K1: pure streaming convert z(f32) -> g_zh(f16).
//   K2: R9's winning shape (4 lanes/edge, 8 edges/warp, 8 LDG.128 in flight)
//       but m_j recomputed from the gathered z_j row via half2 FMA with W
//       held in SHARED memory (no register cost) -> removes the 19.2MB
//       m_j gather stream while keeping occupancy.

#define MAX_N 100000
__device__ static uint4 g_zh[MAX_N * 16];   // fp16 z rows: 256 B/row

#define WARPS_PER_BLOCK 8
#define THREADS (WARPS_PER_BLOCK * 32)

// ---------------- Kernel 1: streaming fp32 -> fp16 convert ----------------
__global__ __launch_bounds__(THREADS) void precompute_kernel(
    const float* __restrict__ z, int n_chunks /* = N*128/8 */)
{
    const int tid     = (int)(blockIdx.x * (unsigned)blockDim.x + threadIdx.x);
    const int nthread = (int)(gridDim.x * (unsigned)blockDim.x);

    uint2* __restrict__ zh2 = reinterpret_cast<uint2*>(g_zh);
    const float4* __restrict__ z4 = reinterpret_cast<const float4*>(z);

    for (int c = tid; c < n_chunks; c += nthread) {
        const float4 v0 = z4[(size_t)c * 2];
        const float4 v1 = z4[(size_t)c * 2 + 1];
        const __half2 h0 = __floats2half2_rn(v0.x, v0.y);
        const __half2 h1 = __floats2half2_rn(v0.z, v0.w);
        const __half2 h2 = __floats2half2_rn(v1.x, v1.y);
        const __half2 h3 = __floats2half2_rn(v1.z, v1.w);
        uint2 p0, p1;
        p0.x = *reinterpret_cast<const unsigned*>(&h0);
        p0.y = *reinterpret_cast<const unsigned*>(&h1);
        p1.x = *reinterpret_cast<const unsigned*>(&h2);
        p1.y = *reinterpret_cast<const unsigned*>(&h3);
        zh2[(size_t)c * 2]     = p0;
        zh2[(size_t)c * 2 + 1] = p1;
    }
    cudaTriggerProgrammaticLaunchCompletion();
}

// ---------------- Kernel 2: per-edge distance + mj + outputs ----------------
// Per uint4 chunk pair: d2 in fp32, mj via hfma2 into a half2 accumulator.
// Wq is the matching 8-coefficient W chunk loaded from shared memory.
__device__ __forceinline__ void chunk_accum(uint4 A, uint4 C, uint4 Wq,
                                            float& d2, __half2& mjacc)
{
    const unsigned* pa = &A.x;
    const unsigned* pc = &C.x;
    const unsigned* pw = &Wq.x;
    #pragma unroll
    for (int k = 0; k < 4; k++) {
        const __half2 ha = *reinterpret_cast<const __half2*>(&pa[k]);
        const __half2 hc = *reinterpret_cast<const __half2*>(&pc[k]);
        const __half2 hw = *reinterpret_cast<const __half2*>(&pw[k]);
        const __half2 d  = __hsub2(ha, hc);
        const float2  df = __half22float2(d);
        d2 += df.x * df.x + df.y * df.y;
        mjacc = __hfma2(hc, hw, mjacc);
    }
}

__global__ __launch_bounds__(THREADS, 5) void gravity_decoder_kernel(
    const int* __restrict__ edge_index,
    const float* __restrict__ W,
    const float* __restrict__ b_ptr,
    float* __restrict__ out,
    int E)
{
    // fp16 W in shared memory: 128 halves = 16 uint4 chunks of 8 coeffs.
    __shared__ uint4 s_w[16];
    if (threadIdx.x < 64) {
        const float2 w2 = reinterpret_cast<const float2*>(W)[threadIdx.x];
        const __half2 h = __floats2half2_rn(w2.x, w2.y);
        reinterpret_cast<unsigned*>(s_w)[threadIdx.x] =
            *reinterpret_cast<const unsigned*>(&h);
    }
    __syncthreads();

    const int lane   = threadIdx.x & 31;
    const int sub    = lane & 3;        // sublane within 4-lane group
    const int group  = lane >> 2;       // 0..7 : which edge of the 8
    const int warp   = (int)((blockIdx.x * (unsigned)blockDim.x + threadIdx.x) >> 5);
    const int nwarps = (int)((gridDim.x * (unsigned)blockDim.x) >> 5);
    const int stride = nwarps * 8;

    const float b = *b_ptr;

    float* __restrict__ out_logits = out;
    float* __restrict__ out_prob   = out + (size_t)E;
    float* __restrict__ out_mj     = out + 2 * (size_t)E;
    float* __restrict__ out_d2     = out + 3 * (size_t)E;

    int e8 = warp * 8;
    if (e8 >= E) {
        cudaGridDependencySynchronize();
        return;
    }

    // Prologue index loads (independent of K1) before the dependency sync.
    int e  = e8 + group;
    int es = (e < E) ? e : (E - 1);
    int src = __ldcs(edge_index + es);
    int dst = __ldcs(edge_index + es + (size_t)E);

    cudaGridDependencySynchronize();   // g_zh valid after this

    for (; e8 < E; e8 += stride) {
        const int  ecur  = e8 + group;
        const bool alive = (ecur < E);

        const uint4* __restrict__ zi = g_zh + (size_t)src * 16;
        const uint4* __restrict__ zj = g_zh + (size_t)dst * 16;

        // 8 gathers in flight per thread (R9 shape)
        const uint4 A0 = zi[sub];
        const uint4 A1 = zi[sub + 4];
        const uint4 A2 = zi[sub + 8];
        const uint4 A3 = zi[sub + 12];
        const uint4 C0 = zj[sub];
        const uint4 C1 = zj[sub + 4];
        const uint4 C2 = zj[sub + 8];
        const uint4 C3 = zj[sub + 12];

        // Prefetch next iteration's indices while gathers are in flight
        const int e8n = e8 + stride;
        if (e8n < E) {
            const int en  = e8n + group;
            const int esn = (en < E) ? en : (E - 1);
            src = __ldcs(edge_index + esn);
            dst = __ldcs(edge_index + esn + (size_t)E);
        }

        float d2 = 0.0f;
        __half2 m0 = __floats2half2_rn(0.f, 0.f);
        __half2 m1 = m0;
        // W chunks from shared memory (broadcast across groups, no reg cost)
        chunk_accum(A0, C0, s_w[sub],      d2, m0);
        chunk_accum(A1, C1, s_w[sub + 4],  d2, m1);
        chunk_accum(A2, C2, s_w[sub + 8],  d2, m0);
        chunk_accum(A3, C3, s_w[sub + 12], d2, m1);

        const float2 f0 = __half22float2(m0);
        const float2 f1 = __half22float2(m1);
        float mj = (f0.x + f0.y) + (f1.x + f1.y);

        // 2-step butterfly within each 4-lane group (both scalars)
        #pragma unroll
        for (int off = 2; off > 0; off >>= 1) {
            d2 += __shfl_xor_sync(0xffffffffu, d2, off);
            mj += __shfl_xor_sync(0xffffffffu, mj, off);
        }

        mj += b;
        d2 += 1e-7f;
        const float logit = mj - __logf(d2);

        if (alive) {
            if (sub == 0)      __stcs(out_logits + ecur, logit);
            else if (sub == 1) __stcs(out_prob + ecur, __fdividef(1.0f, 1.0f + __expf(-logit)));
            else if (sub == 2) __stcs(out_mj + ecur, mj);
            else               __stcs(out_d2 + ecur, d2);
        }
    }
}

extern "C" void kernel_launch(void* const* d_in, const int* in_sizes, int n_in,
                              void* d_out, int out_size)
{
    const float* z   = (const float*)d_in[0];
    const int*   ei  = (const int*)d_in[1];
    const float* W   = (const float*)d_in[2];
    const float* b   = (const float*)d_in[3];
    float*       out = (float*)d_out;

    const int N = in_sizes[0] / 128;
    const int E = in_sizes[1] / 2;

    // K1: streaming convert, persistent grid
    const int n_chunks = N * 16;
    precompute_kernel<<<1480, THREADS>>>(z, n_chunks);

    // K2: 8 edges per warp, PDL overlap with K1 tail
    int blocks2 = (E + WARPS_PER_BLOCK * 8 - 1) / (WARPS_PER_BLOCK * 8);
    if (blocks2 > 4736) blocks2 = 4736;

    cudaLaunchConfig_t cfg = {};
    cfg.gridDim  = dim3((unsigned)blocks2, 1, 1);
    cfg.blockDim = dim3(THREADS, 1, 1);
    cfg.dynamicSmemBytes = 0;
    cfg.stream = 0;
    cudaLaunchAttribute attrs[1];
    attrs[0].id = cudaLaunchAttributeProgrammaticStreamSerialization;
    attrs[0].val.programmaticStreamSerializationAllowed = 1;
    cfg.attrs = attrs;
    cfg.numAttrs = 1;
    cudaLaunchKernelEx(&cfg, gravity_decoder_kernel, ei, W, b, out, E);
}